// round 16
// baseline (speedup 1.0000x reference)
#include <cuda_runtime.h>
#include <cuda_bf16.h>

#define HID   256
#define BATCH 256
#define TLEN  512
#define NS    16
#define SBAT  4096
#define HOR   64
#define GRID  128
#define NTHR  256
#define WREG  65536
#define CTRL  196608
#define SMEM_BYTES (CTRL + 16640 + 1024)

// ---------------- device state ----------------------------------------------
__device__ float g_ec0[BATCH * HID];
__device__ float g_ec1[BATCH * HID];
// h images in MMA fragment layout: u32 idx = ((row16*16+k16)*32+lane)*8 + part*4 + reg
__device__ unsigned g_eA0[2][65536];
__device__ unsigned g_eA1[2][65536];

__device__ float g_dc0[SBAT * HID];
__device__ float g_dc1[SBAT * HID];
__device__ float g_pred[2][SBAT];
__device__ unsigned g_dA0[2][1048576];
__device__ unsigned g_dA1[2][1048576];

// W images, interleaved uint4 {bh0,bh1,bl0,bl1}: mats 0 dWhh0,1 dWih1,2 dWhh1,3-5 enc
__device__ unsigned g_wimg[6][16][16384];

__device__ unsigned g_cnt = 0;
__device__ volatile unsigned g_gen = 0;
__device__ unsigned g_cnt8[8 * 32];
__device__ volatile unsigned g_gen8[8 * 32];

// ---------------- barriers ----------------------------------------------------
__device__ __forceinline__ void gsync() {
    __syncthreads();
    if (threadIdx.x == 0) {
        __threadfence();
        unsigned old = g_gen;
        unsigned a = atomicAdd(&g_cnt, 1u);
        if (a == gridDim.x - 1) { g_cnt = 0; __threadfence(); g_gen = old + 1u; }
        else { while (g_gen == old) { } __threadfence(); }
    }
    __syncthreads();
}
__device__ __forceinline__ void gsyncg(int grp) {
    __syncthreads();
    if (threadIdx.x == 0) {
        __threadfence();
        unsigned old = g_gen8[grp * 32];
        unsigned a = atomicAdd(&g_cnt8[grp * 32], 1u);
        if (a == 15u) { g_cnt8[grp * 32] = 0; __threadfence(); g_gen8[grp * 32] = old + 1u; }
        else { while (g_gen8[grp * 32] == old) { } __threadfence(); }
    }
    __syncthreads();
}

// ---------------- helpers ------------------------------------------------------
__device__ __forceinline__ float sigm(float x) { return 1.0f / (1.0f + expf(-x)); }
__device__ __forceinline__ float rlo(float v) {
    return v - __bfloat162float(__float2bfloat16(v));
}
__device__ __forceinline__ unsigned packbf2(float lo, float hi) {
    unsigned r;
    asm("cvt.rn.bf16x2.f32 %0, %1, %2;" : "=r"(r) : "f"(hi), "f"(lo));
    return r;
}
__device__ __forceinline__ void cpa16(void* dst, const void* src) {
    unsigned d = (unsigned)__cvta_generic_to_shared(dst);
    asm volatile("cp.async.cg.shared.global [%0], [%1], 16;" :: "r"(d), "l"(src));
}
__device__ __forceinline__ void cp_commit() { asm volatile("cp.async.commit_group;" ::: "memory"); }
__device__ __forceinline__ void cp_wait0()  { asm volatile("cp.async.wait_group 0;" ::: "memory"); }

__device__ __forceinline__ void hmma(float (&d)[4], const unsigned (&a)[4],
                                     unsigned b0, unsigned b1) {
    asm volatile(
        "mma.sync.aligned.m16n8k16.row.col.f32.bf16.bf16.f32 "
        "{%0,%1,%2,%3}, {%4,%5,%6,%7}, {%8,%9}, {%0,%1,%2,%3};"
        : "+f"(d[0]), "+f"(d[1]), "+f"(d[2]), "+f"(d[3])
        : "r"(a[0]), "r"(a[1]), "r"(a[2]), "r"(a[3]), "r"(b0), "r"(b1));
}

// A-image block load: hi uint4 + lo uint4 (fully coalesced LDG.128)
__device__ __forceinline__ void ldAblk(unsigned (&ah)[4], unsigned (&al)[4],
                                       const unsigned* A, int row16, int k16, int lane) {
    const uint4* p = (const uint4*)(A + (((row16 * 16 + k16) * 32 + lane) << 3));
    uint4 h = __ldcg(p), l = __ldcg(p + 1);
    ah[0] = h.x; ah[1] = h.y; ah[2] = h.z; ah[3] = h.w;
    al[0] = l.x; al[1] = l.y; al[2] = l.z; al[3] = l.w;
}

// Decoder GEMM: 64-row warp tile (mi=4), K=256, 3-product split, DIST-1 A buffer
// (96 HMMA-issue cycles per k16 > L2 latency, so dist-1 suffices; dist-2 spilled)
__device__ __forceinline__ void dec_gemm(float (&acc)[4][8][4],
    const unsigned* __restrict__ A, const char* __restrict__ w,
    int row16b, int lane)
{
    unsigned ah[2][4][4], al[2][4][4];
#pragma unroll
    for (int mi = 0; mi < 4; ++mi)
        ldAblk(ah[0][mi], al[0][mi], A, row16b + mi, 0, lane);
#pragma unroll 4
    for (int k16 = 0; k16 < 16; ++k16) {
        const int cur = k16 & 1, nx = cur ^ 1;
        if (k16 < 15) {
#pragma unroll
            for (int mi = 0; mi < 4; ++mi)
                ldAblk(ah[nx][mi], al[nx][mi], A, row16b + mi, k16 + 1, lane);
        }
#pragma unroll
        for (int n8 = 0; n8 < 8; ++n8) {
            uint4 b = *(const uint4*)(w + (((k16 * 8 + n8) * 32 + lane) << 4));
#pragma unroll
            for (int mi = 0; mi < 4; ++mi) {
                hmma(acc[mi][n8], ah[cur][mi], b.x, b.y);
                hmma(acc[mi][n8], ah[cur][mi], b.z, b.w);
                hmma(acc[mi][n8], al[cur][mi], b.x, b.y);
            }
        }
    }
}

// ---------------------------------------------------------------------------
__global__ void __launch_bounds__(NTHR, 1)
lstm_all(const float* __restrict__ x,
         const float* __restrict__ eWih0, const float* __restrict__ eWhh0,
         const float* __restrict__ eb0,
         const float* __restrict__ eWih1, const float* __restrict__ eWhh1,
         const float* __restrict__ eb1,
         const float* __restrict__ dWih0, const float* __restrict__ dWhh0,
         const float* __restrict__ db0,
         const float* __restrict__ dWih1, const float* __restrict__ dWhh1,
         const float* __restrict__ db1,
         const float* __restrict__ outW, const float* __restrict__ outb,
         const float* __restrict__ dinit,
         float* __restrict__ out)
{
    extern __shared__ char smem[];
    const int tid = threadIdx.x;
    const int w = tid >> 5, lane = tid & 31;
    const int q = lane & 3, r4 = lane >> 2;
    const int jt = blockIdx.x >> 3, j0 = jt * 16;
    const int grp = blockIdx.x & 7, eRow0 = grp * 32, dRow0 = grp * 512;

    float* gsm0 = (float*)(smem + CTRL);          // [32][65]
    float* gsm1 = gsm0 + 32 * 65;
    float* b0s = (float*)(smem + CTRL + 16640);
    float* w0s = b0s + 64;
    float* b1s = w0s + 64;
    float* ows = b1s + 64;

    // ---- init: build interleaved W fragment images, zero state ----
    {
        const float* Wsrc[6] = { dWhh0, dWih1, dWhh1, eWhh0, eWih1, eWhh1 };
        for (int idx = blockIdx.x * NTHR + tid; idx < 6 * 16 * 16384;
             idx += GRID * NTHR) {
            int e = idx & 16383;
            int r = idx >> 14;
            int ijt = r & 15, m = r >> 4;
            int slot = e & 3, ln = (e >> 2) & 31, blk = e >> 7;
            int part = slot >> 1, kreg = slot & 1;
            int n8 = blk & 7, k16 = blk >> 3;
            int kb = k16 * 16 + (ln & 3) * 2 + kreg * 8;
            int nl = n8 * 8 + (ln >> 2);
            int gate = nl >> 4, j = nl & 15;
            const float* Wr = Wsrc[m] + (size_t)(gate * HID + ijt * 16 + j) * HID;
            float v0 = Wr[kb], v1 = Wr[kb + 1];
            g_wimg[m][ijt][e] = part ? packbf2(rlo(v0), rlo(v1))
                                     : packbf2(v0, v1);
        }
    }
    for (int i = blockIdx.x * NTHR + tid; i < 65536; i += GRID * NTHR) {
        g_eA0[1][i] = 0u; g_eA1[1][i] = 0u;
    }
    for (int i = blockIdx.x * NTHR + tid; i < BATCH * HID; i += GRID * NTHR) {
        g_ec0[i] = 0.f; g_ec1[i] = 0.f;
    }
    gsync();

    // ---- stage encoder W + bias ----
    for (int i = tid; i < 12288; i += NTHR) {
        int m = i >> 12, c = i & 4095;
        cpa16(smem + m * WREG + c * 16, (const char*)&g_wimg[3 + m][jt][0] + c * 16);
    }
    cp_commit();
    for (int i = tid; i < 64; i += NTHR) {
        int g = i >> 4, j = i & 15;
        int gr = g * HID + j0 + j;
        b0s[i] = eb0[gr]; w0s[i] = eWih0[gr]; b1s[i] = eb1[gr];
    }
    cp_wait0();
    gsync();

    // encoder roles: 8 warps = gate(4) x mh(2); each warp does 2 n8-subs
    const int egate = w >> 1, emh = w & 1;
    const int row16e = (eRow0 >> 4) + emh;
    const int erow = tid >> 3, ejp = tid & 7;   // epilogue mapping
    const char* w0m = smem;
    const char* w1m = smem + WREG;
    const char* w2m = smem + 2 * WREG;

    // =========================== encoder (fused, skewed, grp barriers) ========
    for (int p = 0; p <= TLEN; ++p) {
        const unsigned* A0 = g_eA0[(p + 1) & 1];
        const unsigned* A1 = g_eA1[p & 1];
        const bool doL0 = (p < TLEN), doL1 = (p > 0);

        float xv = 0.f;
        if (doL0)
            xv = __ldg(&x[(size_t)(eRow0 + erow) * TLEN + p]);

        float acc0[2][4], acc1[2][4];
#pragma unroll
        for (int s = 0; s < 2; ++s)
#pragma unroll
            for (int d = 0; d < 4; ++d) { acc0[s][d] = 0.f; acc1[s][d] = 0.f; }
        {
            unsigned a0h[3][4], a0l[3][4], a1h[3][4], a1l[3][4];
#pragma unroll
            for (int s = 0; s < 2; ++s) {
                ldAblk(a0h[s], a0l[s], A0, row16e, s, lane);
                if (doL1) ldAblk(a1h[s], a1l[s], A1, row16e, s, lane);
            }
#pragma unroll
            for (int k16 = 0; k16 < 16; ++k16) {
                const int cur = k16 % 3;
                if (k16 < 14) {
                    const int nx = (k16 + 2) % 3;
                    ldAblk(a0h[nx], a0l[nx], A0, row16e, k16 + 2, lane);
                    if (doL1) ldAblk(a1h[nx], a1l[nx], A1, row16e, k16 + 2, lane);
                }
#pragma unroll
                for (int es = 0; es < 2; ++es) {
                    unsigned boff = ((k16 * 8 + egate * 2 + es) * 32 + lane) << 4;
                    if (doL0) {
                        uint4 b = *(const uint4*)(w0m + boff);
                        hmma(acc0[es], a0h[cur], b.x, b.y);
                        hmma(acc0[es], a0h[cur], b.z, b.w);
                        hmma(acc0[es], a0l[cur], b.x, b.y);
                    }
                    if (doL1) {
                        uint4 b = *(const uint4*)(w1m + boff);
                        hmma(acc1[es], a0h[cur], b.x, b.y);
                        hmma(acc1[es], a0h[cur], b.z, b.w);
                        hmma(acc1[es], a0l[cur], b.x, b.y);
                        uint4 c = *(const uint4*)(w2m + boff);
                        hmma(acc1[es], a1h[cur], c.x, c.y);
                        hmma(acc1[es], a1h[cur], c.z, c.w);
                        hmma(acc1[es], a1l[cur], c.x, c.y);
                    }
                }
            }
        }
        if (doL0) {
#pragma unroll
            for (int es = 0; es < 2; ++es)
#pragma unroll
                for (int d = 0; d < 4; ++d)
                    gsm0[(emh * 16 + r4 + (d >> 1) * 8) * 65
                         + egate * 16 + es * 8 + 2 * q + (d & 1)] = acc0[es][d];
        }
        if (doL1) {
#pragma unroll
            for (int es = 0; es < 2; ++es)
#pragma unroll
                for (int d = 0; d < 4; ++d)
                    gsm1[(emh * 16 + r4 + (d >> 1) * 8) * 65
                         + egate * 16 + es * 8 + 2 * q + (d & 1)] = acc1[es][d];
        }
        __syncthreads();

        // cell updates: 256 threads x (2 k-adjacent cells) per layer
        {
            const int ge = eRow0 + erow;
            const int j = 2 * ejp;
            const int lanep = (ge & 7) * 4 + (ejp & 3);
            const int reg = ((ge >> 3) & 1) + 2 * (ejp >> 2);
            const int ibase = (((ge >> 4) * 16 + jt) * 32 + lanep) * 8;
            if (doL0) {
                const float* gr = gsm0 + erow * 65;
                float2 cv = *(float2*)&g_ec0[(size_t)ge * HID + j0 + j];
                float hh[2], c2[2] = {cv.x, cv.y};
#pragma unroll
                for (int e = 0; e < 2; ++e) {
                    int jc = j + e;
                    float gi = gr[jc]      + b0s[jc]      + xv * w0s[jc];
                    float gf = gr[16 + jc] + b0s[16 + jc] + xv * w0s[16 + jc];
                    float gg = gr[32 + jc] + b0s[32 + jc] + xv * w0s[32 + jc];
                    float go = gr[48 + jc] + b0s[48 + jc] + xv * w0s[48 + jc];
                    float cn = sigm(gf) * c2[e] + sigm(gi) * tanhf(gg);
                    c2[e] = cn; hh[e] = sigm(go) * tanhf(cn);
                }
                *(float2*)&g_ec0[(size_t)ge * HID + j0 + j] = make_float2(c2[0], c2[1]);
                unsigned* ib = g_eA0[p & 1] + ibase;
                ib[reg]     = packbf2(hh[0], hh[1]);
                ib[4 + reg] = packbf2(rlo(hh[0]), rlo(hh[1]));
            }
            if (doL1) {
                const float* gr = gsm1 + erow * 65;
                float2 cv = *(float2*)&g_ec1[(size_t)ge * HID + j0 + j];
                float hh[2], c2[2] = {cv.x, cv.y};
#pragma unroll
                for (int e = 0; e < 2; ++e) {
                    int jc = j + e;
                    float gi = gr[jc]      + b1s[jc];
                    float gf = gr[16 + jc] + b1s[16 + jc];
                    float gg = gr[32 + jc] + b1s[32 + jc];
                    float go = gr[48 + jc] + b1s[48 + jc];
                    float cn = sigm(gf) * c2[e] + sigm(gi) * tanhf(gg);
                    c2[e] = cn; hh[e] = sigm(go) * tanhf(cn);
                }
                *(float2*)&g_ec1[(size_t)ge * HID + j0 + j] = make_float2(c2[0], c2[1]);
                unsigned* ib = g_eA1[(p + 1) & 1] + ibase;
                ib[reg]     = packbf2(hh[0], hh[1]);
                ib[4 + reg] = packbf2(rlo(hh[0]), rlo(hh[1]));
            }
        }
        gsyncg(grp);
    }
    gsync();   // global: decoder broadcast reads across groups

    // ============== decoder setup ==============
    for (int i = tid; i < 12288; i += NTHR) {
        int m = i >> 12, c = i & 4095;
        cpa16(smem + m * WREG + c * 16, (const char*)&g_wimg[m][jt][0] + c * 16);
    }
    cp_commit();
    for (int i = tid; i < 64; i += NTHR) {
        int g = i >> 4, j = i & 15;
        int gr = g * HID + j0 + j;
        b0s[i] = db0[gr]; w0s[i] = dWih0[gr]; b1s[i] = db1[gr];
        if (i < 16) ows[i] = outW[j0 + i];
    }
    for (int i = blockIdx.x * NTHR + tid; i < 1048576; i += GRID * NTHR) {
        int r16 = i >> 12, rest = i & 4095;
        int e = (r16 & 15) * 4096 + rest;
        g_dA0[1][i] = __ldcg(&g_eA0[1][e]);
        g_dA1[1][i] = __ldcg(&g_eA1[1][e]);
    }
    for (int i = blockIdx.x * NTHR + tid; i < SBAT * HID; i += GRID * NTHR) {
        int src = i & (BATCH * HID - 1);
        g_dc0[i] = __ldcg(&g_ec0[src]);
        g_dc1[i] = __ldcg(&g_ec1[src]);
    }
    cp_wait0();
    gsync();

    const float outbv = outb[0];
    const int wrow = dRow0 + w * 64;       // 8 warps x 64 rows = 512 rows
    const int row16b = wrow >> 4;

    // =========================== decoder (grp barriers) =======================
    for (int t = 0; t < HOR; ++t) {
        const int rp = (t + 1) & 1, wp = t & 1;

        // ---- layer0 ----
        if (tid < 32) g_pred[wp][dRow0 + jt * 32 + tid] = 0.f;
        {
            float pv[8];
#pragma unroll
            for (int mi = 0; mi < 4; ++mi)
#pragma unroll
                for (int rr = 0; rr < 2; ++rr) {
                    int row = wrow + mi * 16 + r4 + rr * 8;
                    pv[mi * 2 + rr] = (t == 0) ? __ldcg(&dinit[row])
                                               : __ldcg(&g_pred[rp][row]);
                }
            float acc[4][8][4];
#pragma unroll
            for (int mi = 0; mi < 4; ++mi)
#pragma unroll
                for (int n = 0; n < 8; ++n)
#pragma unroll
                    for (int d = 0; d < 4; ++d) acc[mi][n][d] = 0.f;
            dec_gemm(acc, g_dA0[rp], smem, row16b, lane);
#pragma unroll
            for (int mi = 0; mi < 4; ++mi)
#pragma unroll
                for (int rr = 0; rr < 2; ++rr) {
                    int row = wrow + mi * 16 + r4 + rr * 8;
                    float iv = (t == 0) ? pv[mi * 2 + rr] : pv[mi * 2 + rr] + outbv;
                    if (t > 0 && jt == 0 && q == 0)
                        out[(size_t)(row & 255) * (NS * HOR)
                            + (row >> 8) * HOR + (t - 1)] = iv;
                    float h[4];
#pragma unroll
                    for (int hb = 0; hb < 2; ++hb) {
                        int jb = 2 * q + hb * 8;
                        float2 cv = *(float2*)&g_dc0[(size_t)row * HID + j0 + jb];
                        float c2[2] = {cv.x, cv.y};
#pragma unroll
                        for (int e = 0; e < 2; ++e) {
                            int j = jb + e, dr = rr * 2 + e;
                            float gi = acc[mi][hb][dr]     + b0s[j]      + iv * w0s[j];
                            float gf = acc[mi][2 + hb][dr] + b0s[16 + j] + iv * w0s[16 + j];
                            float gg = acc[mi][4 + hb][dr] + b0s[32 + j] + iv * w0s[32 + j];
                            float go = acc[mi][6 + hb][dr] + b0s[48 + j] + iv * w0s[48 + j];
                            float cn = sigm(gf) * c2[e] + sigm(gi) * tanhf(gg);
                            c2[e] = cn; h[hb * 2 + e] = sigm(go) * tanhf(cn);
                        }
                        *(float2*)&g_dc0[(size_t)row * HID + j0 + jb] =
                            make_float2(c2[0], c2[1]);
                    }
                    unsigned* ib = g_dA0[wp]
                        + (((row16b + mi) * 16 + jt) * 32 + lane) * 8;
                    ib[rr]         = packbf2(h[0], h[1]);
                    ib[rr + 2]     = packbf2(h[2], h[3]);
                    ib[4 + rr]     = packbf2(rlo(h[0]), rlo(h[1]));
                    ib[4 + rr + 2] = packbf2(rlo(h[2]), rlo(h[3]));
                }
        }
        gsyncg(grp);

        // ---- layer1 (+ fused projection) ----
        {
            float acc[4][8][4];
#pragma unroll
            for (int mi = 0; mi < 4; ++mi)
#pragma unroll
                for (int n = 0; n < 8; ++n)
#pragma unroll
                    for (int d = 0; d < 4; ++d) acc[mi][n][d] = 0.f;
            dec_gemm(acc, g_dA0[wp], smem + WREG, row16b, lane);
            dec_gemm(acc, g_dA1[rp], smem + 2 * WREG, row16b, lane);
#pragma unroll
            for (int mi = 0; mi < 4; ++mi)
#pragma unroll
                for (int rr = 0; rr < 2; ++rr) {
                    int row = wrow + mi * 16 + r4 + rr * 8;
                    float h[4];
#pragma unroll
                    for (int hb = 0; hb < 2; ++hb) {
                        int jb = 2 * q + hb * 8;
                        float2 cv = *(float2*)&g_dc1[(size_t)row * HID + j0 + jb];
                        float c2[2] = {cv.x, cv.y};
#pragma unroll
                        for (int e = 0; e < 2; ++e) {
                            int j = jb + e, dr = rr * 2 + e;
                            float gi = acc[mi][hb][dr]     + b1s[j];
                            float gf = acc[mi][2 + hb][dr] + b1s[16 + j];
                            float gg = acc[mi][4 + hb][dr] + b1s[32 + j];
                            float go = acc[mi][6 + hb][dr] + b1s[48 + j];
                            float cn = sigm(gf) * c2[e] + sigm(gi) * tanhf(gg);
                            c2[e] = cn; h[hb * 2 + e] = sigm(go) * tanhf(cn);
                        }
                        *(float2*)&g_dc1[(size_t)row * HID + j0 + jb] =
                            make_float2(c2[0], c2[1]);
                    }
                    unsigned* ib = g_dA1[wp]
                        + (((row16b + mi) * 16 + jt) * 32 + lane) * 8;
                    ib[rr]         = packbf2(h[0], h[1]);
                    ib[rr + 2]     = packbf2(h[2], h[3]);
                    ib[4 + rr]     = packbf2(rlo(h[0]), rlo(h[1]));
                    ib[4 + rr + 2] = packbf2(rlo(h[2]), rlo(h[3]));
                    float psum = h[0] * ows[2 * q] + h[1] * ows[2 * q + 1]
                               + h[2] * ows[2 * q + 8] + h[3] * ows[2 * q + 9];
                    psum += __shfl_xor_sync(0xffffffffu, psum, 1);
                    psum += __shfl_xor_sync(0xffffffffu, psum, 2);
                    if (q == 0) atomicAdd(&g_pred[wp][row], psum);
                }
        }
        gsyncg(grp);
    }

    // ---- tail output (rows of own group) ----
    if (tid < 32) {
        int row = dRow0 + jt * 32 + tid;
        float v = __ldcg(&g_pred[(HOR - 1) & 1][row]) + outbv;
        out[(size_t)(row & 255) * (NS * HOR) + (row >> 8) * HOR + (HOR - 1)] = v;
    }
}

// ---------------------------------------------------------------------------
extern "C" void kernel_launch(void* const* d_in, const int* in_sizes, int n_in,
                              void* d_out, int out_size)
{
    (void)in_sizes; (void)n_in; (void)out_size;
    const float* x     = (const float*)d_in[0];
    const float* eWih0 = (const float*)d_in[1];
    const float* eWhh0 = (const float*)d_in[2];
    const float* eb0   = (const float*)d_in[3];
    const float* eWih1 = (const float*)d_in[4];
    const float* eWhh1 = (const float*)d_in[5];
    const float* eb1   = (const float*)d_in[6];
    const float* dWih0 = (const float*)d_in[7];
    const float* dWhh0 = (const float*)d_in[8];
    const float* db0   = (const float*)d_in[9];
    const float* dWih1 = (const float*)d_in[10];
    const float* dWhh1 = (const float*)d_in[11];
    const float* db1   = (const float*)d_in[12];
    const float* outW  = (const float*)d_in[13];
    const float* outb  = (const float*)d_in[14];
    const float* dinit = (const float*)d_in[15];
    float* out = (float*)d_out;

    cudaFuncSetAttribute(lstm_all, cudaFuncAttributeMaxDynamicSharedMemorySize,
                         SMEM_BYTES);
    lstm_all<<<GRID, NTHR, SMEM_BYTES>>>(x, eWih0, eWhh0, eb0, eWih1, eWhh1, eb1,
                                         dWih0, dWhh0, db0, dWih1, dWhh1, db1,
                                         outW, outb, dinit, out);
}

// round 17
// speedup vs baseline: 1.1340x; 1.1340x over previous
#include <cuda_runtime.h>
#include <cuda_bf16.h>

#define HID   256
#define BATCH 256
#define TLEN  512
#define NS    16
#define SBAT  4096
#define HOR   64
#define GRID  128
#define NTHR  256
#define WREG  65536
#define CTRL  196608
#define SMEM_BYTES (CTRL + 16640 + 1024)

// ---------------- device state ----------------------------------------------
__device__ float g_ec0[BATCH * HID];
__device__ float g_ec1[BATCH * HID];
// h images in MMA fragment layout: u32 idx = ((row16*16+k16)*32+lane)*8 + part*4 + reg
__device__ unsigned g_eA0[2][65536];
__device__ unsigned g_eA1[2][65536];

// decoder c in PRIVATE per-thread layout: [(cta*8+w)*32+lane][32 cells]
__device__ float g_pc0[GRID * 8 * 32 * 32];
__device__ float g_pc1[GRID * 8 * 32 * 32];
__device__ float g_pred[2][SBAT];
__device__ unsigned g_dA0[2][1048576];
__device__ unsigned g_dA1[2][1048576];

// W images, interleaved uint4 {bh0,bh1,bl0,bl1}: mats 0 dWhh0,1 dWih1,2 dWhh1,3-5 enc
__device__ unsigned g_wimg[6][16][16384];

__device__ unsigned g_cnt = 0;
__device__ volatile unsigned g_gen = 0;
__device__ unsigned g_cnt8[8 * 32];
__device__ volatile unsigned g_gen8[8 * 32];

// ---------------- barriers ----------------------------------------------------
__device__ __forceinline__ void gsync() {
    __syncthreads();
    if (threadIdx.x == 0) {
        __threadfence();
        unsigned old = g_gen;
        unsigned a = atomicAdd(&g_cnt, 1u);
        if (a == gridDim.x - 1) { g_cnt = 0; __threadfence(); g_gen = old + 1u; }
        else { while (g_gen == old) { } __threadfence(); }
    }
    __syncthreads();
}
__device__ __forceinline__ void gsyncg(int grp) {
    __syncthreads();
    if (threadIdx.x == 0) {
        __threadfence();
        unsigned old = g_gen8[grp * 32];
        unsigned a = atomicAdd(&g_cnt8[grp * 32], 1u);
        if (a == 15u) { g_cnt8[grp * 32] = 0; __threadfence(); g_gen8[grp * 32] = old + 1u; }
        else { while (g_gen8[grp * 32] == old) { } __threadfence(); }
    }
    __syncthreads();
}

// ---------------- helpers ------------------------------------------------------
__device__ __forceinline__ float ex2f(float x) {
    float r; asm("ex2.approx.f32 %0, %1;" : "=f"(r) : "f"(x)); return r;
}
__device__ __forceinline__ float rcpf(float x) {
    float r; asm("rcp.approx.f32 %0, %1;" : "=f"(r) : "f"(x)); return r;
}
__device__ __forceinline__ float sigm(float x) {
    return rcpf(1.0f + ex2f(-1.4426950408889634f * x));
}
__device__ __forceinline__ float tanhfast(float x) {
    return 1.0f - 2.0f * rcpf(1.0f + ex2f(2.8853900817779268f * x));
}
__device__ __forceinline__ float rlo(float v) {
    return v - __bfloat162float(__float2bfloat16(v));
}
__device__ __forceinline__ unsigned packbf2(float lo, float hi) {
    unsigned r;
    asm("cvt.rn.bf16x2.f32 %0, %1, %2;" : "=r"(r) : "f"(hi), "f"(lo));
    return r;
}
__device__ __forceinline__ void cpa16(void* dst, const void* src) {
    unsigned d = (unsigned)__cvta_generic_to_shared(dst);
    asm volatile("cp.async.cg.shared.global [%0], [%1], 16;" :: "r"(d), "l"(src));
}
__device__ __forceinline__ void cp_commit() { asm volatile("cp.async.commit_group;" ::: "memory"); }
__device__ __forceinline__ void cp_wait0()  { asm volatile("cp.async.wait_group 0;" ::: "memory"); }

__device__ __forceinline__ void hmma(float (&d)[4], const unsigned (&a)[4],
                                     unsigned b0, unsigned b1) {
    asm volatile(
        "mma.sync.aligned.m16n8k16.row.col.f32.bf16.bf16.f32 "
        "{%0,%1,%2,%3}, {%4,%5,%6,%7}, {%8,%9}, {%0,%1,%2,%3};"
        : "+f"(d[0]), "+f"(d[1]), "+f"(d[2]), "+f"(d[3])
        : "r"(a[0]), "r"(a[1]), "r"(a[2]), "r"(a[3]), "r"(b0), "r"(b1));
}

// A-image block load: hi uint4 + lo uint4 (fully coalesced LDG.128)
__device__ __forceinline__ void ldAblk(unsigned (&ah)[4], unsigned (&al)[4],
                                       const unsigned* A, int row16, int k16, int lane) {
    const uint4* p = (const uint4*)(A + (((row16 * 16 + k16) * 32 + lane) << 3));
    uint4 h = __ldcg(p), l = __ldcg(p + 1);
    ah[0] = h.x; ah[1] = h.y; ah[2] = h.z; ah[3] = h.w;
    al[0] = l.x; al[1] = l.y; al[2] = l.z; al[3] = l.w;
}

// Decoder GEMM: 64-row warp tile (mi=4), K=256, 3-product split, dist-1 A buffer
__device__ __forceinline__ void dec_gemm(float (&acc)[4][8][4],
    const unsigned* __restrict__ A, const char* __restrict__ w,
    int row16b, int lane)
{
    unsigned ah[2][4][4], al[2][4][4];
#pragma unroll
    for (int mi = 0; mi < 4; ++mi)
        ldAblk(ah[0][mi], al[0][mi], A, row16b + mi, 0, lane);
#pragma unroll 4
    for (int k16 = 0; k16 < 16; ++k16) {
        const int cur = k16 & 1, nx = cur ^ 1;
        if (k16 < 15) {
#pragma unroll
            for (int mi = 0; mi < 4; ++mi)
                ldAblk(ah[nx][mi], al[nx][mi], A, row16b + mi, k16 + 1, lane);
        }
#pragma unroll
        for (int n8 = 0; n8 < 8; ++n8) {
            uint4 b = *(const uint4*)(w + (((k16 * 8 + n8) * 32 + lane) << 4));
#pragma unroll
            for (int mi = 0; mi < 4; ++mi) {
                hmma(acc[mi][n8], ah[cur][mi], b.x, b.y);
                hmma(acc[mi][n8], ah[cur][mi], b.z, b.w);
                hmma(acc[mi][n8], al[cur][mi], b.x, b.y);
            }
        }
    }
}

// ---------------------------------------------------------------------------
__global__ void __launch_bounds__(NTHR, 1)
lstm_all(const float* __restrict__ x,
         const float* __restrict__ eWih0, const float* __restrict__ eWhh0,
         const float* __restrict__ eb0,
         const float* __restrict__ eWih1, const float* __restrict__ eWhh1,
         const float* __restrict__ eb1,
         const float* __restrict__ dWih0, const float* __restrict__ dWhh0,
         const float* __restrict__ db0,
         const float* __restrict__ dWih1, const float* __restrict__ dWhh1,
         const float* __restrict__ db1,
         const float* __restrict__ outW, const float* __restrict__ outb,
         const float* __restrict__ dinit,
         float* __restrict__ out)
{
    extern __shared__ char smem[];
    const int tid = threadIdx.x;
    const int w = tid >> 5, lane = tid & 31;
    const int q = lane & 3, r4 = lane >> 2;
    const int jt = blockIdx.x >> 3, j0 = jt * 16;
    const int grp = blockIdx.x & 7, eRow0 = grp * 32, dRow0 = grp * 512;

    float* gsm0 = (float*)(smem + CTRL);          // [32][65]
    float* gsm1 = gsm0 + 32 * 65;
    float* b0s = (float*)(smem + CTRL + 16640);
    float* w0s = b0s + 64;
    float* b1s = w0s + 64;
    float* ows = b1s + 64;

    // ---- init: build interleaved W fragment images, zero state ----
    {
        const float* Wsrc[6] = { dWhh0, dWih1, dWhh1, eWhh0, eWih1, eWhh1 };
        for (int idx = blockIdx.x * NTHR + tid; idx < 6 * 16 * 16384;
             idx += GRID * NTHR) {
            int e = idx & 16383;
            int r = idx >> 14;
            int ijt = r & 15, m = r >> 4;
            int slot = e & 3, ln = (e >> 2) & 31, blk = e >> 7;
            int part = slot >> 1, kreg = slot & 1;
            int n8 = blk & 7, k16 = blk >> 3;
            int kb = k16 * 16 + (ln & 3) * 2 + kreg * 8;
            int nl = n8 * 8 + (ln >> 2);
            int gate = nl >> 4, j = nl & 15;
            const float* Wr = Wsrc[m] + (size_t)(gate * HID + ijt * 16 + j) * HID;
            float v0 = Wr[kb], v1 = Wr[kb + 1];
            g_wimg[m][ijt][e] = part ? packbf2(rlo(v0), rlo(v1))
                                     : packbf2(v0, v1);
        }
    }
    for (int i = blockIdx.x * NTHR + tid; i < 65536; i += GRID * NTHR) {
        g_eA0[1][i] = 0u; g_eA1[1][i] = 0u;
    }
    for (int i = blockIdx.x * NTHR + tid; i < BATCH * HID; i += GRID * NTHR) {
        g_ec0[i] = 0.f; g_ec1[i] = 0.f;
    }
    gsync();

    // ---- stage encoder W + bias ----
    for (int i = tid; i < 12288; i += NTHR) {
        int m = i >> 12, c = i & 4095;
        cpa16(smem + m * WREG + c * 16, (const char*)&g_wimg[3 + m][jt][0] + c * 16);
    }
    cp_commit();
    for (int i = tid; i < 64; i += NTHR) {
        int g = i >> 4, j = i & 15;
        int gr = g * HID + j0 + j;
        b0s[i] = eb0[gr]; w0s[i] = eWih0[gr]; b1s[i] = eb1[gr];
    }
    cp_wait0();
    gsync();

    // encoder roles: 8 warps = gate(4) x mh(2); each warp does 2 n8-subs
    const int egate = w >> 1, emh = w & 1;
    const int row16e = (eRow0 >> 4) + emh;
    const int erow = tid >> 3, ejp = tid & 7;   // epilogue mapping
    const char* w0m = smem;
    const char* w1m = smem + WREG;
    const char* w2m = smem + 2 * WREG;

    // =========================== encoder (fused, skewed, grp barriers) ========
    for (int p = 0; p <= TLEN; ++p) {
        const unsigned* A0 = g_eA0[(p + 1) & 1];
        const unsigned* A1 = g_eA1[p & 1];
        const bool doL0 = (p < TLEN), doL1 = (p > 0);

        float xv = 0.f;
        if (doL0)
            xv = __ldg(&x[(size_t)(eRow0 + erow) * TLEN + p]);

        float acc0[2][4], acc1[2][4];
#pragma unroll
        for (int s = 0; s < 2; ++s)
#pragma unroll
            for (int d = 0; d < 4; ++d) { acc0[s][d] = 0.f; acc1[s][d] = 0.f; }
        {
            unsigned a0h[3][4], a0l[3][4], a1h[3][4], a1l[3][4];
#pragma unroll
            for (int s = 0; s < 2; ++s) {
                ldAblk(a0h[s], a0l[s], A0, row16e, s, lane);
                if (doL1) ldAblk(a1h[s], a1l[s], A1, row16e, s, lane);
            }
#pragma unroll
            for (int k16 = 0; k16 < 16; ++k16) {
                const int cur = k16 % 3;
                if (k16 < 14) {
                    const int nx = (k16 + 2) % 3;
                    ldAblk(a0h[nx], a0l[nx], A0, row16e, k16 + 2, lane);
                    if (doL1) ldAblk(a1h[nx], a1l[nx], A1, row16e, k16 + 2, lane);
                }
#pragma unroll
                for (int es = 0; es < 2; ++es) {
                    unsigned boff = ((k16 * 8 + egate * 2 + es) * 32 + lane) << 4;
                    if (doL0) {
                        uint4 b = *(const uint4*)(w0m + boff);
                        hmma(acc0[es], a0h[cur], b.x, b.y);
                        hmma(acc0[es], a0h[cur], b.z, b.w);
                        hmma(acc0[es], a0l[cur], b.x, b.y);
                    }
                    if (doL1) {
                        uint4 b = *(const uint4*)(w1m + boff);
                        hmma(acc1[es], a0h[cur], b.x, b.y);
                        hmma(acc1[es], a0h[cur], b.z, b.w);
                        hmma(acc1[es], a0l[cur], b.x, b.y);
                        uint4 c = *(const uint4*)(w2m + boff);
                        hmma(acc1[es], a1h[cur], c.x, c.y);
                        hmma(acc1[es], a1h[cur], c.z, c.w);
                        hmma(acc1[es], a1l[cur], c.x, c.y);
                    }
                }
            }
        }
        if (doL0) {
#pragma unroll
            for (int es = 0; es < 2; ++es)
#pragma unroll
                for (int d = 0; d < 4; ++d)
                    gsm0[(emh * 16 + r4 + (d >> 1) * 8) * 65
                         + egate * 16 + es * 8 + 2 * q + (d & 1)] = acc0[es][d];
        }
        if (doL1) {
#pragma unroll
            for (int es = 0; es < 2; ++es)
#pragma unroll
                for (int d = 0; d < 4; ++d)
                    gsm1[(emh * 16 + r4 + (d >> 1) * 8) * 65
                         + egate * 16 + es * 8 + 2 * q + (d & 1)] = acc1[es][d];
        }
        __syncthreads();

        // cell updates: 256 threads x (2 k-adjacent cells) per layer
        {
            const int ge = eRow0 + erow;
            const int j = 2 * ejp;
            const int lanep = (ge & 7) * 4 + (ejp & 3);
            const int reg = ((ge >> 3) & 1) + 2 * (ejp >> 2);
            const int ibase = (((ge >> 4) * 16 + jt) * 32 + lanep) * 8;
            if (doL0) {
                const float* gr = gsm0 + erow * 65;
                float2 cv = *(float2*)&g_ec0[(size_t)ge * HID + j0 + j];
                float hh[2], c2[2] = {cv.x, cv.y};
#pragma unroll
                for (int e = 0; e < 2; ++e) {
                    int jc = j + e;
                    float gi = gr[jc]      + b0s[jc]      + xv * w0s[jc];
                    float gf = gr[16 + jc] + b0s[16 + jc] + xv * w0s[16 + jc];
                    float gg = gr[32 + jc] + b0s[32 + jc] + xv * w0s[32 + jc];
                    float go = gr[48 + jc] + b0s[48 + jc] + xv * w0s[48 + jc];
                    float cn = sigm(gf) * c2[e] + sigm(gi) * tanhfast(gg);
                    c2[e] = cn; hh[e] = sigm(go) * tanhfast(cn);
                }
                *(float2*)&g_ec0[(size_t)ge * HID + j0 + j] = make_float2(c2[0], c2[1]);
                unsigned* ib = g_eA0[p & 1] + ibase;
                ib[reg]     = packbf2(hh[0], hh[1]);
                ib[4 + reg] = packbf2(rlo(hh[0]), rlo(hh[1]));
            }
            if (doL1) {
                const float* gr = gsm1 + erow * 65;
                float2 cv = *(float2*)&g_ec1[(size_t)ge * HID + j0 + j];
                float hh[2], c2[2] = {cv.x, cv.y};
#pragma unroll
                for (int e = 0; e < 2; ++e) {
                    int jc = j + e;
                    float gi = gr[jc]      + b1s[jc];
                    float gf = gr[16 + jc] + b1s[16 + jc];
                    float gg = gr[32 + jc] + b1s[32 + jc];
                    float go = gr[48 + jc] + b1s[48 + jc];
                    float cn = sigm(gf) * c2[e] + sigm(gi) * tanhfast(gg);
                    c2[e] = cn; hh[e] = sigm(go) * tanhfast(cn);
                }
                *(float2*)&g_ec1[(size_t)ge * HID + j0 + j] = make_float2(c2[0], c2[1]);
                unsigned* ib = g_eA1[(p + 1) & 1] + ibase;
                ib[reg]     = packbf2(hh[0], hh[1]);
                ib[4 + reg] = packbf2(rlo(hh[0]), rlo(hh[1]));
            }
        }
        gsyncg(grp);
    }
    gsync();   // global: decoder broadcast reads across groups

    // ============== decoder setup ==============
    for (int i = tid; i < 12288; i += NTHR) {
        int m = i >> 12, c = i & 4095;
        cpa16(smem + m * WREG + c * 16, (const char*)&g_wimg[m][jt][0] + c * 16);
    }
    cp_commit();
    for (int i = tid; i < 64; i += NTHR) {
        int g = i >> 4, j = i & 15;
        int gr = g * HID + j0 + j;
        b0s[i] = db0[gr]; w0s[i] = dWih0[gr]; b1s[i] = db1[gr];
        if (i < 16) ows[i] = outW[j0 + i];
    }
    for (int i = blockIdx.x * NTHR + tid; i < 1048576; i += GRID * NTHR) {
        int r16 = i >> 12, rest = i & 4095;
        int e = (r16 & 15) * 4096 + rest;
        g_dA0[1][i] = __ldcg(&g_eA0[1][e]);
        g_dA1[1][i] = __ldcg(&g_eA1[1][e]);
    }
    // private c layout population: cell (row, jg) -> owner (block,w,lane,pos)
    for (int i = blockIdx.x * NTHR + tid; i < SBAT * HID; i += GRID * NTHR) {
        int row = i >> 8, jg = i & 255;
        int ggrp = row >> 9, ww = (row >> 6) & 7;
        int low = row & 63;
        int mi = low >> 4, l16 = low & 15;
        int rr = l16 >> 3, rr4 = l16 & 7;
        int jjt = jg >> 4, jl = jg & 15;
        int hb = jl >> 3, r8 = jl & 7;
        int qq = r8 >> 1, ee = r8 & 1;
        int blk = jjt * 8 + ggrp;
        int lanep = rr4 * 4 + qq;
        int pos = mi * 8 + rr * 4 + hb * 2 + ee;
        size_t pidx = ((size_t)(blk * 8 + ww) * 32 + lanep) * 32 + pos;
        int src = (row & 255) * HID + jg;
        g_pc0[pidx] = __ldcg(&g_ec0[src]);
        g_pc1[pidx] = __ldcg(&g_ec1[src]);
    }
    cp_wait0();
    gsync();

    const float outbv = outb[0];
    const int wrow = dRow0 + w * 64;       // 8 warps x 64 rows = 512 rows
    const int row16b = wrow >> 4;
    float* pc0 = g_pc0 + ((size_t)(blockIdx.x * 8 + w) * 32 + lane) * 32;
    float* pc1 = g_pc1 + ((size_t)(blockIdx.x * 8 + w) * 32 + lane) * 32;

    // =========================== decoder (grp barriers) =======================
    for (int t = 0; t < HOR; ++t) {
        const int rp = (t + 1) & 1, wp = t & 1;

        // ---- layer0 ----
        if (tid < 32) g_pred[wp][dRow0 + jt * 32 + tid] = 0.f;
        {
            float pv[8];
#pragma unroll
            for (int mi = 0; mi < 4; ++mi)
#pragma unroll
                for (int rr = 0; rr < 2; ++rr) {
                    int row = wrow + mi * 16 + r4 + rr * 8;
                    pv[mi * 2 + rr] = (t == 0) ? __ldcg(&dinit[row])
                                               : __ldcg(&g_pred[rp][row]);
                }
            float acc[4][8][4];
#pragma unroll
            for (int mi = 0; mi < 4; ++mi)
#pragma unroll
                for (int n = 0; n < 8; ++n)
#pragma unroll
                    for (int d = 0; d < 4; ++d) acc[mi][n][d] = 0.f;
            dec_gemm(acc, g_dA0[rp], smem, row16b, lane);
#pragma unroll
            for (int mi = 0; mi < 4; ++mi) {
                float h[2][4];
#pragma unroll
                for (int rr = 0; rr < 2; ++rr) {
                    int row = wrow + mi * 16 + r4 + rr * 8;
                    float iv = (t == 0) ? pv[mi * 2 + rr] : pv[mi * 2 + rr] + outbv;
                    if (t > 0 && jt == 0 && q == 0)
                        out[(size_t)(row & 255) * (NS * HOR)
                            + (row >> 8) * HOR + (t - 1)] = iv;
                    float4 cv = *(float4*)(pc0 + mi * 8 + rr * 4);
                    float c4[4] = {cv.x, cv.y, cv.z, cv.w};
#pragma unroll
                    for (int hb = 0; hb < 2; ++hb)
#pragma unroll
                        for (int e = 0; e < 2; ++e) {
                            int j = 2 * q + e + hb * 8;
                            int dr = rr * 2 + e, ci = hb * 2 + e;
                            float gi = acc[mi][hb][dr]     + b0s[j]      + iv * w0s[j];
                            float gf = acc[mi][2 + hb][dr] + b0s[16 + j] + iv * w0s[16 + j];
                            float gg = acc[mi][4 + hb][dr] + b0s[32 + j] + iv * w0s[32 + j];
                            float go = acc[mi][6 + hb][dr] + b0s[48 + j] + iv * w0s[48 + j];
                            float cn = sigm(gf) * c4[ci] + sigm(gi) * tanhfast(gg);
                            c4[ci] = cn;
                            h[rr][ci] = sigm(go) * tanhfast(cn);
                        }
                    *(float4*)(pc0 + mi * 8 + rr * 4) =
                        make_float4(c4[0], c4[1], c4[2], c4[3]);
                }
                unsigned* ib = g_dA0[wp] + (((row16b + mi) * 16 + jt) * 32 + lane) * 8;
                uint4 hi = make_uint4(packbf2(h[0][0], h[0][1]), packbf2(h[1][0], h[1][1]),
                                      packbf2(h[0][2], h[0][3]), packbf2(h[1][2], h[1][3]));
                uint4 lo = make_uint4(packbf2(rlo(h[0][0]), rlo(h[0][1])),
                                      packbf2(rlo(h[1][0]), rlo(h[1][1])),
                                      packbf2(rlo(h[0][2]), rlo(h[0][3])),
                                      packbf2(rlo(h[1][2]), rlo(h[1][3])));
                *(uint4*)(ib)     = hi;
                *(uint4*)(ib + 4) = lo;
            }
        }
        gsyncg(grp);

        // ---- layer1 (+ fused projection) ----
        {
            float acc[4][8][4];
#pragma unroll
            for (int mi = 0; mi < 4; ++mi)
#pragma unroll
                for (int n = 0; n < 8; ++n)
#pragma unroll
                    for (int d = 0; d < 4; ++d) acc[mi][n][d] = 0.f;
            dec_gemm(acc, g_dA0[wp], smem + WREG, row16b, lane);
            dec_gemm(acc, g_dA1[rp], smem + 2 * WREG, row16b, lane);
#pragma unroll
            for (int mi = 0; mi < 4; ++mi) {
                float h[2][4];
#pragma unroll
                for (int rr = 0; rr < 2; ++rr) {
                    int row = wrow + mi * 16 + r4 + rr * 8;
                    float4 cv = *(float4*)(pc1 + mi * 8 + rr * 4);
                    float c4[4] = {cv.x, cv.y, cv.z, cv.w};
#pragma unroll
                    for (int hb = 0; hb < 2; ++hb)
#pragma unroll
                        for (int e = 0; e < 2; ++e) {
                            int j = 2 * q + e + hb * 8;
                            int dr = rr * 2 + e, ci = hb * 2 + e;
                            float gi = acc[mi][hb][dr]     + b1s[j];
                            float gf = acc[mi][2 + hb][dr] + b1s[16 + j];
                            float gg = acc[mi][4 + hb][dr] + b1s[32 + j];
                            float go = acc[mi][6 + hb][dr] + b1s[48 + j];
                            float cn = sigm(gf) * c4[ci] + sigm(gi) * tanhfast(gg);
                            c4[ci] = cn;
                            h[rr][ci] = sigm(go) * tanhfast(cn);
                        }
                    *(float4*)(pc1 + mi * 8 + rr * 4) =
                        make_float4(c4[0], c4[1], c4[2], c4[3]);
                    float psum = h[rr][0] * ows[2 * q] + h[rr][1] * ows[2 * q + 1]
                               + h[rr][2] * ows[2 * q + 8] + h[rr][3] * ows[2 * q + 9];
                    psum += __shfl_xor_sync(0xffffffffu, psum, 1);
                    psum += __shfl_xor_sync(0xffffffffu, psum, 2);
                    if (q == 0) atomicAdd(&g_pred[wp][row], psum);
                }
                unsigned* ib = g_dA1[wp] + (((row16b + mi) * 16 + jt) * 32 + lane) * 8;
                uint4 hi = make_uint4(packbf2(h[0][0], h[0][1]), packbf2(h[1][0], h[1][1]),
                                      packbf2(h[0][2], h[0][3]), packbf2(h[1][2], h[1][3]));
                uint4 lo = make_uint4(packbf2(rlo(h[0][0]), rlo(h[0][1])),
                                      packbf2(rlo(h[1][0]), rlo(h[1][1])),
                                      packbf2(rlo(h[0][2]), rlo(h[0][3])),
                                      packbf2(rlo(h[1][2]), rlo(h[1][3])));
                *(uint4*)(ib)     = hi;
                *(uint4*)(ib + 4) = lo;
            }
        }
        gsyncg(grp);
    }

    // ---- tail output (rows of own group) ----
    if (tid < 32) {
        int row = dRow0 + jt * 32 + tid;
        float v = __ldcg(&g_pred[(HOR - 1) & 1][row]) + outbv;
        out[(size_t)(row & 255) * (NS * HOR) + (row >> 8) * HOR + (HOR - 1)] = v;
    }
}

// ---------------------------------------------------------------------------
extern "C" void kernel_launch(void* const* d_in, const int* in_sizes, int n_in,
                              void* d_out, int out_size)
{
    (void)in_sizes; (void)n_in; (void)out_size;
    const float* x     = (const float*)d_in[0];
    const float* eWih0 = (const float*)d_in[1];
    const float* eWhh0 = (const float*)d_in[2];
    const float* eb0   = (const float*)d_in[3];
    const float* eWih1 = (const float*)d_in[4];
    const float* eWhh1 = (const float*)d_in[5];
    const float* eb1   = (const float*)d_in[6];
    const float* dWih0 = (const float*)d_in[7];
    const float* dWhh0 = (const float*)d_in[8];
    const float* db0   = (const float*)d_in[9];
    const float* dWih1 = (const float*)d_in[10];
    const float* dWhh1 = (const float*)d_in[11];
    const float* db1   = (const float*)d_in[12];
    const float* outW  = (const float*)d_in[13];
    const float* outb  = (const float*)d_in[14];
    const float* dinit = (const float*)d_in[15];
    float* out = (float*)d_out;

    cudaFuncSetAttribute(lstm_all, cudaFuncAttributeMaxDynamicSharedMemorySize,
                         SMEM_BYTES);
    lstm_all<<<GRID, NTHR, SMEM_BYTES>>>(x, eWih0, eWhh0, eb0, eWih1, eWhh1, eb1,
                                         dWih0, dWhh0, db0, dWih1, dWhh1, db1,
                                         outW, outb, dinit, out);
}